// round 10
// baseline (speedup 1.0000x reference)
#include <cuda_runtime.h>
#include <cuda_fp16.h>
#include <math.h>
#include <stdint.h>

// ---------------------------------------------------------------------------
// Problem constants
// ---------------------------------------------------------------------------
#define BB   16
#define NN   512
#define DIM  256
#define NH   8
#define HD   32
#define ROWS (BB*NN)          // 8192
#define MAXD 128
#define NG   32
#define LOG2E 1.4426950408889634f

// scratch layout (float units)
#define OFF_BIAS 0                           // half [16*8*512*512] = 16777216 f
#define OFF_HS32 16777216                    // ln1 out f32 [8192,256]
#define OFF_HSH  (OFF_HS32 + 2097152)        // ln1 out half
#define OFF_QKV  (OFF_HSH  + 1048576)        // half [8192,768]
#define OFF_CTXH (OFF_QKV  + 3145728)        // half [8192,256]
#define OFF_HATT (OFF_CTXH + 1048576)        // f32  [8192,256]
#define OFF_H2H  (OFF_HATT + 2097152)        // half [8192,256]
#define OFF_F1H  (OFF_H2H  + 1048576)        // half [8192,1024]
#define OFF_WH   (OFF_F1H  + 4194304)        // half weights (786432 halves)
#define OFF_TBL  (OFF_WH   + 393216)         // rbf table (2048 floats)
#define SCRATCH_FLOATS (OFF_TBL + 2048)

__device__ float g_scratch[SCRATCH_FLOATS];

// half-weight sub-offsets (half units within OFF_WH)
#define WH_IPW 0
#define WH_OPW 196608
#define WH_W1  262144
#define WH_W2  524288

// ---------------------------------------------------------------------------
// helpers
// ---------------------------------------------------------------------------
__device__ __forceinline__ void cp16(void* s, const void* g) {
    unsigned sa = (unsigned)__cvta_generic_to_shared(s);
    asm volatile("cp.async.cg.shared.global [%0], [%1], 16;" :: "r"(sa), "l"(g));
}
#define CP_COMMIT() asm volatile("cp.async.commit_group;")

__device__ __forceinline__ uint32_t smem_u32(const void* p) {
    return (uint32_t)__cvta_generic_to_shared(p);
}

__device__ __forceinline__ void mma_f16(float* d, const uint32_t* a, uint32_t b0, uint32_t b1) {
    asm volatile(
        "mma.sync.aligned.m16n8k16.row.col.f32.f16.f16.f32 "
        "{%0,%1,%2,%3}, {%4,%5,%6,%7}, {%8,%9}, {%0,%1,%2,%3};\n"
        : "+f"(d[0]), "+f"(d[1]), "+f"(d[2]), "+f"(d[3])
        : "r"(a[0]), "r"(a[1]), "r"(a[2]), "r"(a[3]), "r"(b0), "r"(b1));
}

#define LDSM_X4(r0,r1,r2,r3,addr) \
    asm volatile("ldmatrix.sync.aligned.m8n8.x4.shared.b16 {%0,%1,%2,%3}, [%4];" \
        : "=r"(r0), "=r"(r1), "=r"(r2), "=r"(r3) : "r"(addr))
#define LDSM_X4_T(r0,r1,r2,r3,addr) \
    asm volatile("ldmatrix.sync.aligned.m8n8.x4.trans.shared.b16 {%0,%1,%2,%3}, [%4];" \
        : "=r"(r0), "=r"(r1), "=r"(r2), "=r"(r3) : "r"(addr))
#define LDSM_X2_T(r0,r1,addr) \
    asm volatile("ldmatrix.sync.aligned.m8n8.x2.trans.shared.b16 {%0,%1}, [%2];" \
        : "=r"(r0), "=r"(r1) : "r"(addr))

__device__ __forceinline__ uint32_t packh2(float x, float y) {
    __half2 h = __floats2half2_rn(x, y);
    return *reinterpret_cast<uint32_t*>(&h);
}
__device__ __forceinline__ uint32_t h2u(__half2 h) {
    return *reinterpret_cast<uint32_t*>(&h);
}
// P = 2^(s + b), all f16x2
__device__ __forceinline__ uint32_t hexp2_add(uint32_t s, uint32_t b) {
    uint32_t r;
    asm("{ .reg .b32 t;\n add.f16x2 t, %1, %2;\n ex2.approx.f16x2 %0, t; }"
        : "=r"(r) : "r"(s), "r"(b));
    return r;
}

// ---------------------------------------------------------------------------
// weight fp32 -> fp16 conversion (once per launch; 393216 half2)
// ---------------------------------------------------------------------------
__global__ void convert_w(const float* __restrict__ ipw, const float* __restrict__ opw,
                          const float* __restrict__ w1,  const float* __restrict__ w2,
                          __half2* __restrict__ wh) {
    int i = blockIdx.x * 256 + threadIdx.x;
    const int n0 = 98304, n1 = 32768, n2 = 131072;
    float2 v;
    if (i < n0)                 v = ((const float2*)ipw)[i];
    else if (i < n0 + n1)       v = ((const float2*)opw)[i - n0];
    else if (i < n0 + n1 + n2)  v = ((const float2*)w1)[i - n0 - n1];
    else                        v = ((const float2*)w2)[i - n0 - n1 - n2];
    wh[i] = __floats2half2_rn(v.x, v.y);
}

// ---------------------------------------------------------------------------
// RBF table (values pre-multiplied by LOG2E for the ex2 path)
// ---------------------------------------------------------------------------
__global__ void build_rbf_table(const float* __restrict__ rbf_w,
                                __half2* __restrict__ tbl) {
    int uidx = blockIdx.x * 128 + threadIdx.x;    // 0..1023
    float u = (float)uidx * (1.0f / 32.0f);
    float acc[NH] = {};
    #pragma unroll
    for (int g = 0; g < NG; g++) {
        float d = u - (float)g;
        float r = __expf(-0.5f * d * d);
        #pragma unroll
        for (int h = 0; h < NH; h++) acc[h] += r * rbf_w[h * NG + g];
    }
    #pragma unroll
    for (int p = 0; p < 4; p++)
        tbl[uidx * 4 + p] = __floats2half2_rn(acc[2 * p] * LOG2E, acc[2 * p + 1] * LOG2E);
}

// ---------------------------------------------------------------------------
// LayerNorm: writes half (GEMM A input) and optional fp32 (residual)
// ---------------------------------------------------------------------------
__global__ void ln_kernel(const float* __restrict__ x,
                          const float* __restrict__ g,
                          const float* __restrict__ be,
                          __half* __restrict__ out_h,
                          float* __restrict__ out_f) {
    int row = blockIdx.x;
    int t   = threadIdx.x;
    float v = x[row * DIM + t];

    float s = v, sq = v * v;
    #pragma unroll
    for (int off = 16; off; off >>= 1) {
        s  += __shfl_xor_sync(0xffffffffu, s,  off);
        sq += __shfl_xor_sync(0xffffffffu, sq, off);
    }
    __shared__ float rs[8], rq[8];
    int warp = t >> 5, lane = t & 31;
    if (lane == 0) { rs[warp] = s; rq[warp] = sq; }
    __syncthreads();
    float ts = 0.f, tq = 0.f;
    #pragma unroll
    for (int w = 0; w < 8; w++) { ts += rs[w]; tq += rq[w]; }

    float mean = ts * (1.0f / DIM);
    float var  = tq * (1.0f / DIM) - mean * mean;
    float inv  = rsqrtf(var + 1e-5f);
    float val  = (v - mean) * inv * g[t] + be[t];
    out_h[row * DIM + t] = __float2half(val);
    if (out_f) out_f[row * DIM + t] = val;
}

// ---------------------------------------------------------------------------
// Bias kernel v4: table lerp; outputs pre-multiplied by LOG2E.
// block = (b, 8 q-rows), 128 threads, 4 k/thread.
// ---------------------------------------------------------------------------
__global__ __launch_bounds__(128)
void bias_kernel(const int*   __restrict__ dm,
                 const float* __restrict__ d3,
                 const float* __restrict__ dist_emb,
                 const __half2* __restrict__ tbl,
                 const float* __restrict__ rbf_b,
                 __half* __restrict__ bias) {
    int blk = blockIdx.x;              // 0..1023
    int b   = blk >> 6;
    int q0  = (blk & 63) * 8;
    int t   = threadIdx.x;

    __shared__ __align__(16) __half2 tb[1024 * 4];   // 16 KB (already *LOG2E)
    __shared__ __align__(16) __half2 eb[MAXD * 4];   // 4 KB

    {
        const float4* src = (const float4*)tbl;
        float4* dst = (float4*)tb;
        #pragma unroll
        for (int i = 0; i < 8; i++) dst[t + i * 128] = src[t + i * 128];
    }
    for (int i = t; i < MAXD * 4; i += 128) {
        int d = i >> 2, p = i & 3;
        eb[i] = __floats2half2_rn((dist_emb[d * NH + 2 * p]     + rbf_b[2 * p])     * LOG2E,
                                  (dist_emb[d * NH + 2 * p + 1] + rbf_b[2 * p + 1]) * LOG2E);
    }
    __syncthreads();

    const float scale = (31.0f / 20.0f) * 32.0f;
    const int k = t * 4;

    for (int qq = 0; qq < 8; qq++) {
        int q = q0 + qq;
        size_t base = ((size_t)(b * NN + q)) * NN;

        float4 dd  = *(const float4*)&d3[base + k];
        int4   di4 = *(const int4*)&dm[base + k];
        float uf[4] = {dd.x * scale, dd.y * scale, dd.z * scale, dd.w * scale};
        int   di[4];
        di[0] = min(max(di4.x, 0), MAXD - 1);
        di[1] = min(max(di4.y, 0), MAXD - 1);
        di[2] = min(max(di4.z, 0), MAXD - 1);
        di[3] = min(max(di4.w, 0), MAXD - 1);

        __half2 acc[4][4];
        #pragma unroll
        for (int kk = 0; kk < 4; kk++) {
            int   idx = (int)uf[kk];
            float fr  = uf[kk] - (float)idx;
            __half2 frh = __float2half2_rn(fr);
            const __half2* t0 = &tb[idx * 4];
            const __half2* t1 = t0 + 4;
            const __half2* e  = &eb[di[kk] * 4];
            #pragma unroll
            for (int p = 0; p < 4; p++) {
                __half2 lerp = __hfma2(frh, __hsub2(t1[p], t0[p]), t0[p]);
                acc[kk][p] = __hadd2(e[p], lerp);
            }
        }

        #pragma unroll
        for (int p = 0; p < 4; p++) {
            uint2 lo, hi;
            lo.x = h2u(__lows2half2 (acc[0][p], acc[1][p]));
            lo.y = h2u(__lows2half2 (acc[2][p], acc[3][p]));
            hi.x = h2u(__highs2half2(acc[0][p], acc[1][p]));
            hi.y = h2u(__highs2half2(acc[2][p], acc[3][p]));
            size_t i0 = ((size_t)(b * NH + 2 * p) * NN + q) * NN + k;
            *(uint2*)&bias[i0]                   = lo;
            *(uint2*)&bias[i0 + (size_t)NN * NN] = hi;
        }
    }
}

// ---------------------------------------------------------------------------
// FP16 tensor-core flash attention v3: ex2.f16x2 softmax (log2e pre-folded),
// l computed via ones-column appended to V (exact fp32 row sums from mma).
// ---------------------------------------------------------------------------
#define KVSTRIDE 40   // halves per row (32 data + 8 pad; col 32 = ones)

__global__ __launch_bounds__(256)
void attn_kernel(const __half* __restrict__ qkv,
                 const __half* __restrict__ bias,
                 __half* __restrict__ ctx) {
    const int qt = blockIdx.x;
    const int h  = blockIdx.y;
    const int b  = blockIdx.z;
    const int q0 = qt * 128;
    const int t  = threadIdx.x;
    const int wid  = t >> 5;
    const int lane = t & 31;
    const int g  = lane >> 2;
    const int tt = lane & 3;
    const int wr = wid * 16;

    __shared__ __align__(16) __half Qs[128 * KVSTRIDE];
    __shared__ __align__(16) __half Ks[2 * 64 * KVSTRIDE];
    __shared__ __align__(16) __half Vs[2 * 64 * KVSTRIDE];

    // ones column (col 32 = 1.0, cols 33..39 = 0) for both V buffers
    if (t < 128)
        *(uint4*)&Vs[t * KVSTRIDE + 32] = make_uint4(0x00003C00u, 0u, 0u, 0u);

    #pragma unroll
    for (int r = 0; r < 2; r++) {
        int id = t * 2 + r;
        int row = id >> 2, seg = id & 3;
        cp16(&Qs[row * KVSTRIDE + seg * 8],
             qkv + (size_t)(b * NN + q0 + row) * 768 + h * HD + seg * 8);
    }
    {
        int row = t >> 2, seg = t & 3;
        size_t src = (size_t)(b * NN + row) * 768 + h * HD + seg * 8;
        cp16(&Ks[row * KVSTRIDE + seg * 8], qkv + src + 256);
        cp16(&Vs[row * KVSTRIDE + seg * 8], qkv + src + 512);
    }
    CP_COMMIT();

    float O[4][4] = {};
    float Ol[4] = {};          // ones-column accumulator (l in [0]/[2] at tt=0)
    uint32_t qa[2][4];
    bool qloaded = false;

    const __half* bptr0 = bias + ((size_t)(b * NH + h) * NN + (q0 + wr + g)) * NN;
    const __half* bptr1 = bptr0 + 8 * (size_t)NN;

    for (int kt = 0; kt < 8; kt++) {
        int buf = kt & 1;
        if (kt + 1 < 8) {
            int nb = (kt + 1) & 1;
            int k0n = (kt + 1) * 64;
            int row = t >> 2, seg = t & 3;
            size_t src = (size_t)(b * NN + k0n + row) * 768 + h * HD + seg * 8;
            cp16(&Ks[nb * 64 * KVSTRIDE + row * KVSTRIDE + seg * 8], qkv + src + 256);
            cp16(&Vs[nb * 64 * KVSTRIDE + row * KVSTRIDE + seg * 8], qkv + src + 512);
            CP_COMMIT();
            asm volatile("cp.async.wait_group 1;");
        } else {
            asm volatile("cp.async.wait_group 0;");
        }
        __syncthreads();

        if (!qloaded) {
            qloaded = true;
            #pragma unroll
            for (int ks = 0; ks < 2; ks++) {
                uint32_t a = smem_u32(&Qs[(wr + (lane & 15)) * KVSTRIDE + ks * 16 + 8 * (lane >> 4)]);
                LDSM_X4(qa[ks][0], qa[ks][1], qa[ks][2], qa[ks][3], a);
            }
        }

        const __half* Kb = Ks + buf * 64 * KVSTRIDE;
        const __half* Vb = Vs + buf * 64 * KVSTRIDE;

        // ---- S = Q @ K^T (logits already in log2 units) ----
        float S[8][4];
        #pragma unroll
        for (int nt = 0; nt < 8; nt++) { S[nt][0] = S[nt][1] = S[nt][2] = S[nt][3] = 0.f; }

        #pragma unroll
        for (int ks = 0; ks < 2; ks++) {
            #pragma unroll
            for (int p = 0; p < 4; p++) {
                int rowk = 16 * p + 8 * (lane >> 4) + (lane & 7);
                int colk = ks * 16 + 8 * ((lane >> 3) & 1);
                uint32_t b0, b1, b2, b3;
                LDSM_X4(b0, b1, b2, b3, smem_u32(&Kb[rowk * KVSTRIDE + colk]));
                mma_f16(S[2 * p],     qa[ks], b0, b1);
                mma_f16(S[2 * p + 1], qa[ks], b2, b3);
            }
        }

        // ---- P = 2^(S + bias) in f16x2 ----
        int k0 = kt * 64;
        uint32_t P01[8], P23[8];
        #pragma unroll
        for (int nt = 0; nt < 8; nt++) {
            uint32_t b01 = *(const uint32_t*)(bptr0 + k0 + nt * 8 + 2 * tt);
            uint32_t b23 = *(const uint32_t*)(bptr1 + k0 + nt * 8 + 2 * tt);
            P01[nt] = hexp2_add(packh2(S[nt][0], S[nt][1]), b01);
            P23[nt] = hexp2_add(packh2(S[nt][2], S[nt][3]), b23);
        }

        // ---- O += P @ V (ones column gives l) ----
        #pragma unroll
        for (int j = 0; j < 4; j++) {
            uint32_t pa[4];
            pa[0] = P01[2 * j];
            pa[1] = P23[2 * j];
            pa[2] = P01[2 * j + 1];
            pa[3] = P23[2 * j + 1];
            int rowv = j * 16 + (lane & 7) + 8 * ((lane >> 3) & 1);
            #pragma unroll
            for (int q2 = 0; q2 < 2; q2++) {
                int colv = q2 * 16 + 8 * (lane >> 4);
                uint32_t b0, b1, b2, b3;
                LDSM_X4_T(b0, b1, b2, b3, smem_u32(&Vb[rowv * KVSTRIDE + colv]));
                mma_f16(O[2 * q2],     pa, b0, b1);
                mma_f16(O[2 * q2 + 1], pa, b2, b3);
            }
            {   // ones column tile (cols 32..39)
                uint32_t c0, c1;
                LDSM_X2_T(c0, c1, smem_u32(&Vb[rowv * KVSTRIDE + 32]));
                mma_f16(Ol, pa, c0, c1);
            }
        }
        __syncthreads();
    }

    // l lives at tt=0 of each quad (col 32)
    float l0 = __shfl_sync(0xffffffffu, Ol[0], lane & 28);
    float l1 = __shfl_sync(0xffffffffu, Ol[2], lane & 28);
    float inv0 = 1.0f / l0, inv1 = 1.0f / l1;
    #pragma unroll
    for (int nt = 0; nt < 4; nt++) {
        int col = h * HD + nt * 8 + 2 * tt;
        *(__half2*)&ctx[(size_t)(b * NN + q0 + wr + g)     * DIM + col] =
            __floats2half2_rn(O[nt][0] * inv0, O[nt][1] * inv0);
        *(__half2*)&ctx[(size_t)(b * NN + q0 + wr + g + 8) * DIM + col] =
            __floats2half2_rn(O[nt][2] * inv1, O[nt][3] * inv1);
    }
}

// ---------------------------------------------------------------------------
// FP16 tensor-core GEMM v2: BM=128, BN=64, BK=64, 256 threads (8 warps 4x2),
// warp tile 32x32.
// ---------------------------------------------------------------------------
#define HSTRIDE 72
#define ATILE_H (128 * HSTRIDE)
#define BTILE_H (64  * HSTRIDE)

template<bool GELU, bool RES, bool OUTH>
__global__ __launch_bounds__(256)
void h16_gemm(const __half* __restrict__ A,
              const __half* __restrict__ Bw,
              const float* __restrict__ bias,
              const float* __restrict__ res,
              void* __restrict__ Cv,
              int Nn, int K, float qscale) {
    extern __shared__ __half hsm[];
    __half* As = hsm;
    __half* Bs = hsm + 2 * ATILE_H;

    const int t    = threadIdx.x;
    const int bm   = blockIdx.x * 128;
    const int bn   = blockIdx.y * 64;
    const int wid  = t >> 5;
    const int lane = t & 31;
    const int wm   = (wid >> 1) * 32;
    const int wn   = (wid & 1) * 32;
    const int g    = lane >> 2;
    const int tt   = lane & 3;

    float acc[2][4][4];
    #pragma unroll
    for (int i = 0; i < 2; i++)
        #pragma unroll
        for (int j = 0; j < 4; j++)
            #pragma unroll
            for (int c = 0; c < 4; c++) acc[i][j][c] = 0.f;

    const int niter = K >> 6;

    #pragma unroll
    for (int i = 0; i < 4; i++) {
        int task = t + i * 256;
        int row = task >> 3, seg = task & 7;
        cp16(&As[row * HSTRIDE + seg * 8], A + (size_t)(bm + row) * K + seg * 8);
    }
    #pragma unroll
    for (int i = 0; i < 2; i++) {
        int task = t + i * 256;
        int row = task >> 3, seg = task & 7;
        cp16(&Bs[row * HSTRIDE + seg * 8], Bw + (size_t)(bn + row) * K + seg * 8);
    }
    CP_COMMIT();

    for (int it = 0; it < niter; it++) {
        if (it + 1 < niter) {
            int buf = (it + 1) & 1;
            int k0  = (it + 1) * 64;
            #pragma unroll
            for (int i = 0; i < 4; i++) {
                int task = t + i * 256;
                int row = task >> 3, seg = task & 7;
                cp16(&As[buf * ATILE_H + row * HSTRIDE + seg * 8],
                     A + (size_t)(bm + row) * K + k0 + seg * 8);
            }
            #pragma unroll
            for (int i = 0; i < 2; i++) {
                int task = t + i * 256;
                int row = task >> 3, seg = task & 7;
                cp16(&Bs[buf * BTILE_H + row * HSTRIDE + seg * 8],
                     Bw + (size_t)(bn + row) * K + k0 + seg * 8);
            }
            CP_COMMIT();
            asm volatile("cp.async.wait_group 1;");
        } else {
            asm volatile("cp.async.wait_group 0;");
        }
        __syncthreads();

        const __half* Ab = As + (it & 1) * ATILE_H;
        const __half* Bb = Bs + (it & 1) * BTILE_H;

        #pragma unroll
        for (int ks = 0; ks < 4; ks++) {
            uint32_t af[2][4];
            #pragma unroll
            for (int mt = 0; mt < 2; mt++) {
                uint32_t a = smem_u32(&Ab[(wm + mt * 16 + (lane & 15)) * HSTRIDE
                                          + ks * 16 + 8 * (lane >> 4)]);
                LDSM_X4(af[mt][0], af[mt][1], af[mt][2], af[mt][3], a);
            }
            #pragma unroll
            for (int pp = 0; pp < 2; pp++) {
                int rowk = wn + pp * 16 + 8 * (lane >> 4) + (lane & 7);
                int colk = ks * 16 + 8 * ((lane >> 3) & 1);
                uint32_t b0, b1, b2, b3;
                LDSM_X4(b0, b1, b2, b3, smem_u32(&Bb[rowk * HSTRIDE + colk]));
                #pragma unroll
                for (int mt = 0; mt < 2; mt++) {
                    mma_f16(acc[mt][2 * pp],     af[mt], b0, b1);
                    mma_f16(acc[mt][2 * pp + 1], af[mt], b2, b3);
                }
            }
        }
        __syncthreads();
    }

    #pragma unroll
    for (int mt = 0; mt < 2; mt++) {
        #pragma unroll
        for (int nt = 0; nt < 4; nt++) {
            int row0 = bm + wm + mt * 16 + g;
            int col  = bn + wn + nt * 8 + 2 * tt;
            float b0 = bias[col], b1 = bias[col + 1];

            float v00 = acc[mt][nt][0] + b0;
            float v01 = acc[mt][nt][1] + b1;
            float v10 = acc[mt][nt][2] + b0;
            float v11 = acc[mt][nt][3] + b1;
            if (GELU) {
                v00 = 0.5f * v00 * (1.0f + erff(v00 * 0.70710678118654752f));
                v01 = 0.5f * v01 * (1.0f + erff(v01 * 0.70710678118654752f));
                v10 = 0.5f * v10 * (1.0f + erff(v10 * 0.70710678118654752f));
                v11 = 0.5f * v11 * (1.0f + erff(v11 * 0.70710678118654752f));
            }
            if (RES) {
                float2 r0 = *(const float2*)&res[(size_t)row0 * Nn + col];
                float2 r1 = *(const float2*)&res[(size_t)(row0 + 8) * Nn + col];
                v00 += r0.x; v01 += r0.y;
                v10 += r1.x; v11 += r1.y;
            }
            if (OUTH) {
                float s = (col < DIM) ? qscale : 1.0f;
                __half* C = (__half*)Cv;
                *(__half2*)&C[(size_t)row0 * Nn + col]       = __floats2half2_rn(v00 * s, v01 * s);
                *(__half2*)&C[(size_t)(row0 + 8) * Nn + col] = __floats2half2_rn(v10 * s, v11 * s);
            } else {
                float* C = (float*)Cv;
                float2 o0; o0.x = v00; o0.y = v01;
                float2 o1; o1.x = v10; o1.y = v11;
                *(float2*)&C[(size_t)row0 * Nn + col]       = o0;
                *(float2*)&C[(size_t)(row0 + 8) * Nn + col] = o1;
            }
        }
    }
}

#define GEMM_SMEM ((2 * ATILE_H + 2 * BTILE_H) * sizeof(__half))   // 55296 B

// ---------------------------------------------------------------------------
// launch (single stream)
// ---------------------------------------------------------------------------
extern "C" void kernel_launch(void* const* d_in, const int* in_sizes, int n_in,
                              void* d_out, int out_size) {
    const float* x    = (const float*)d_in[0];
    const int*   dm   = (const int*)  d_in[2];
    const float* d3   = (const float*)d_in[3];
    const float* n1g  = (const float*)d_in[4];
    const float* n1b  = (const float*)d_in[5];
    const float* ipw  = (const float*)d_in[6];
    const float* ipb  = (const float*)d_in[7];
    const float* opw  = (const float*)d_in[8];
    const float* opb  = (const float*)d_in[9];
    const float* demb = (const float*)d_in[10];
    const float* rbfw = (const float*)d_in[11];
    const float* rbfb = (const float*)d_in[12];
    const float* n2g  = (const float*)d_in[13];
    const float* n2b  = (const float*)d_in[14];
    const float* w1   = (const float*)d_in[15];
    const float* b1   = (const float*)d_in[16];
    const float* w2   = (const float*)d_in[17];
    const float* b2   = (const float*)d_in[18];
    float* out = (float*)d_out;

    float* scratch = nullptr;
    cudaGetSymbolAddress((void**)&scratch, g_scratch);
    __half*  bias  = (__half*)(scratch + OFF_BIAS);
    float*   hs32  = scratch + OFF_HS32;
    __half*  hsh   = (__half*)(scratch + OFF_HSH);
    __half*  qkv   = (__half*)(scratch + OFF_QKV);
    __half*  ctxh  = (__half*)(scratch + OFF_CTXH);
    float*   hatt  = scratch + OFF_HATT;
    __half*  h2h   = (__half*)(scratch + OFF_H2H);
    __half*  f1h   = (__half*)(scratch + OFF_F1H);
    __half*  wh    = (__half*)(scratch + OFF_WH);
    __half2* tbl   = (__half2*)(scratch + OFF_TBL);
    __half* ipw_h = wh + WH_IPW;
    __half* opw_h = wh + WH_OPW;
    __half* w1_h  = wh + WH_W1;
    __half* w2_h  = wh + WH_W2;

    static bool attr_done = false;
    if (!attr_done) {
        cudaFuncSetAttribute(h16_gemm<false, false, true >, cudaFuncAttributeMaxDynamicSharedMemorySize, GEMM_SMEM);
        cudaFuncSetAttribute(h16_gemm<false, true,  false>, cudaFuncAttributeMaxDynamicSharedMemorySize, GEMM_SMEM);
        cudaFuncSetAttribute(h16_gemm<true,  false, true >, cudaFuncAttributeMaxDynamicSharedMemorySize, GEMM_SMEM);
        attr_done = true;
    }

    // Q pre-scale includes log2e (ex2 path)
    const float qscale = LOG2E * 0.17677669529663687f;

    // 0a. rbf lookup table (tiny)
    build_rbf_table<<<8, 128>>>(rbfw, tbl);
    // 0b. weights -> half
    convert_w<<<1536, 256>>>(ipw, opw, w1, w2, (__half2*)wh);
    // 1. h = LN1(x): half for GEMM + f32 residual
    ln_kernel<<<ROWS, 256>>>(x, n1g, n1b, hsh, hs32);
    // 2. qkv = h @ in_proj_w^T + b  (half out, Q pre-scaled by log2e/sqrt(hd))
    h16_gemm<false, false, true><<<dim3(ROWS / 128, 768 / 64), 256, GEMM_SMEM>>>(
        hsh, ipw_h, ipb, nullptr, qkv, 768, 256, qscale);
    // 3. bias[b,h,q,k] via table lerp (pre-scaled by log2e)
    bias_kernel<<<1024, 128>>>(dm, d3, demb, tbl, rbfb, bias);
    // 4. attention -> ctx half
    attn_kernel<<<dim3(NN / 128, NH, BB), 256>>>(qkv, bias, ctxh);
    // 5. hatt = ctx @ out_proj^T + b + h   (f32 out)
    h16_gemm<false, true, false><<<dim3(ROWS / 128, 256 / 64), 256, GEMM_SMEM>>>(
        ctxh, opw_h, opb, hs32, hatt, 256, 256, 1.0f);
    // 6. h2 = LN2(hatt)
    ln_kernel<<<ROWS, 256>>>(hatt, n2g, n2b, h2h, nullptr);
    // 7. f1 = gelu(h2 @ w1^T + b1)  (half out)
    h16_gemm<true, false, true><<<dim3(ROWS / 128, 1024 / 64), 256, GEMM_SMEM>>>(
        h2h, w1_h, b1, nullptr, f1h, 1024, 256, 1.0f);
    // 8. out = f1 @ w2^T + b2 + hatt  (f32 out)
    h16_gemm<false, true, false><<<dim3(ROWS / 128, 256 / 64), 256, GEMM_SMEM>>>(
        f1h, w2_h, b2, hatt, out, 256, 1024, 1.0f);
}